// round 1
// baseline (speedup 1.0000x reference)
#include <cuda_runtime.h>
#include <math.h>

#define BATCH   1024
#define D       64
#define NLEAVES 64
#define VOC     50000
#define NREL    7
#define KTOT    4224     // 4096 kron + 64 L-linear + 64 R-linear
#define NCHUNK  66       // 64 kron chunks + 2 linear chunks
#define LPITCH  68       // padded row pitch (floats) for transposed L/R tiles (16B aligned)

// -------- device scratch (no runtime allocation allowed) --------
__device__ float g_vocT[VOC * D];                    // 12.8 MB transposed vocab
__device__ float g_XA[2 * BATCH * NLEAVES * D];      // 33.5 MB ping
__device__ float g_XB[2 * BATCH * (NLEAVES / 2) * D];// 16.8 MB pong
__device__ float g_Wc[KTOT * D];                     // compose weights, [k][e]
__device__ float g_Wf[KTOT * D];                     // final weights,   [k][e]
__device__ float g_bc[D];
__device__ float g_bf[D];

// -------- vocab transpose: (64, 50000) -> (50000, 64) --------
__global__ void k_transpose_voc(const float* __restrict__ voc_w) {
    __shared__ float tile[64][65];
    int v0 = blockIdx.x * 64;
    for (int idx = threadIdx.x; idx < 64 * 64; idx += 256) {
        int d = idx >> 6, vv = idx & 63;
        int v = v0 + vv;
        tile[vv][d] = (v < VOC) ? voc_w[d * VOC + v] : 0.f;
    }
    __syncthreads();
    for (int idx = threadIdx.x; idx < 64 * 64; idx += 256) {
        int vv = idx >> 6, d = idx & 63;
        int v = v0 + vv;
        if (v < VOC) g_vocT[v * D + d] = tile[vv][d];
    }
}

// -------- weight prep: transpose + concat [cpst | cps_L | cps_R] as [k][e] --------
__global__ void k_prep(const float* __restrict__ cps_w,  const float* __restrict__ cps_b,
                       const float* __restrict__ cpst_w, const float* __restrict__ cpst_b,
                       const float* __restrict__ cpr_w,  const float* __restrict__ cpr_b,
                       const float* __restrict__ cprt_w, const float* __restrict__ cprt_b) {
    int t = blockIdx.x * 256 + threadIdx.x;
    if (t < KTOT * D) {
        int e = t / KTOT, k = t % KTOT;
        float vc, vf;
        if (k < 4096) { vc = cpst_w[e * 4096 + k]; vf = cprt_w[e * 4096 + k]; }
        else          { int f = k - 4096; vc = cps_w[e * 128 + f]; vf = cpr_w[e * 128 + f]; }
        g_Wc[k * D + e] = vc;
        g_Wf[k * D + e] = vf;
    }
    if (t < D) { g_bc[t] = cps_b[t] + cpst_b[t]; g_bf[t] = cpr_b[t] + cprt_b[t]; }
}

// -------- embedding gather: X0[tree][b][leaf][d] = vocT[idx][d] + voc_b[d] --------
__global__ void k_embed(const int* __restrict__ left, const int* __restrict__ right,
                        const float* __restrict__ voc_b) {
    int t = blockIdx.x * 256 + threadIdx.x;           // 2*1024*64 nodes * 16 float4
    int node = t >> 4;
    int c = (t & 15) * 4;
    int tree = node >> 16;
    int bl = node & 0xFFFF;
    int idx = tree ? right[bl] : left[bl];
    float4 v  = *(const float4*)(g_vocT + idx * D + c);
    float4 bb = *(const float4*)(voc_b + c);
    v.x += bb.x; v.y += bb.y; v.z += bb.z; v.w += bb.w;
    *(float4*)(g_XA + node * D + c) = v;
}

// -------- one tree-compose level --------
// Block = 64 pair-nodes, 256 threads, output tile 64x64.
// out[m,e] = tanh( sum_i L_i[m] * (sum_j L_j[m]*Wc[(i,j),e]) + sum_f [L|R]_f*Wlin[f,e] + b[e] )
__global__ void __launch_bounds__(256) k_compose(const float* __restrict__ Xin,
                                                 float* __restrict__ Xout,
                                                 const float* __restrict__ W,
                                                 const float* __restrict__ bias,
                                                 int n_out) {
    extern __shared__ float smem[];
    float* LsT = smem;                    // [64 f][LPITCH m]
    float* RsT = smem + 64 * LPITCH;
    float* Bs  = smem + 2 * 64 * LPITCH;  // [64 j][64 e]
    const int t  = threadIdx.x;
    const int g0 = blockIdx.x * 64;

    // load 64 nodes (L||R contiguous: children 2p, 2p+1), transpose into SMEM
    {
        int m  = t >> 2;
        int fb = (t & 3) * 32;
        int g  = g0 + m;
        int p  = g % n_out;
        int bp = g / n_out;
        const float* src = Xin + (bp * 2 * n_out + 2 * p) * D;
#pragma unroll
        for (int it = 0; it < 8; it++) {
            int f = fb + it * 4;
            float4 v = *(const float4*)(src + f);
            float* dst = (f < 64) ? (LsT + f * LPITCH + m) : (RsT + (f - 64) * LPITCH + m);
            dst[0] = v.x; dst[LPITCH] = v.y; dst[2 * LPITCH] = v.z; dst[3 * LPITCH] = v.w;
        }
    }

    const int tm = (t >> 4) * 4;   // 0..60
    const int te = (t & 15) * 4;   // 0..60
    float acc[4][4] = {};

    for (int chunk = 0; chunk < NCHUNK; chunk++) {
        __syncthreads();
#pragma unroll
        for (int r = 0; r < 4; r++) {
            int i4 = r * 256 + t;
            ((float4*)Bs)[i4] = ((const float4*)(W + chunk * 4096))[i4];
        }
        __syncthreads();

        const float* A = (chunk == 65) ? RsT : LsT;
        float P[4][4] = {};
#pragma unroll 8
        for (int j = 0; j < 64; j++) {
            float4 a = *(const float4*)(A + j * LPITCH + tm);
            float4 b = *(const float4*)(Bs + j * 64 + te);
            P[0][0] += a.x * b.x; P[0][1] += a.x * b.y; P[0][2] += a.x * b.z; P[0][3] += a.x * b.w;
            P[1][0] += a.y * b.x; P[1][1] += a.y * b.y; P[1][2] += a.y * b.z; P[1][3] += a.y * b.w;
            P[2][0] += a.z * b.x; P[2][1] += a.z * b.y; P[2][2] += a.z * b.z; P[2][3] += a.z * b.w;
            P[3][0] += a.w * b.x; P[3][1] += a.w * b.y; P[3][2] += a.w * b.z; P[3][3] += a.w * b.w;
        }
        if (chunk < 64) {
            float4 ai = *(const float4*)(LsT + chunk * LPITCH + tm);
            float am[4] = {ai.x, ai.y, ai.z, ai.w};
#pragma unroll
            for (int mm = 0; mm < 4; mm++)
#pragma unroll
                for (int nn = 0; nn < 4; nn++) acc[mm][nn] += am[mm] * P[mm][nn];
        } else {
#pragma unroll
            for (int mm = 0; mm < 4; mm++)
#pragma unroll
                for (int nn = 0; nn < 4; nn++) acc[mm][nn] += P[mm][nn];
        }
    }

    float4 bv = *(const float4*)(bias + te);
    float bb[4] = {bv.x, bv.y, bv.z, bv.w};
#pragma unroll
    for (int mm = 0; mm < 4; mm++) {
        float4 o;
        o.x = tanhf(acc[mm][0] + bb[0]);
        o.y = tanhf(acc[mm][1] + bb[1]);
        o.z = tanhf(acc[mm][2] + bb[2]);
        o.w = tanhf(acc[mm][3] + bb[3]);
        *(float4*)(Xout + (g0 + tm + mm) * D + te) = o;
    }
}

// -------- final: cpr + cprt (kron = l (x) r) + leaky_relu + logits + softmax --------
__global__ void __launch_bounds__(256) k_final(const float* __restrict__ X,
                                               float* __restrict__ out,
                                               const float* __restrict__ W,
                                               const float* __restrict__ bias,
                                               const float* __restrict__ sm_w,
                                               const float* __restrict__ sm_b) {
    extern __shared__ float smem[];
    float* LsT = smem;
    float* RsT = smem + 64 * LPITCH;
    float* Bs  = smem + 2 * 64 * LPITCH;   // reused as actT[e][m] in epilogue
    const int t  = threadIdx.x;
    const int g0 = blockIdx.x * 64;

    {
        int m  = t >> 2;
        int fb = (t & 3) * 32;
        int b  = g0 + m;
#pragma unroll
        for (int it = 0; it < 8; it++) {
            int f = fb + it * 4;
            const float* src = (f < 64) ? (X + b * D + f) : (X + (BATCH + b) * D + (f - 64));
            float4 v = *(const float4*)src;
            float* dst = (f < 64) ? (LsT + f * LPITCH + m) : (RsT + (f - 64) * LPITCH + m);
            dst[0] = v.x; dst[LPITCH] = v.y; dst[2 * LPITCH] = v.z; dst[3 * LPITCH] = v.w;
        }
    }

    const int tm = (t >> 4) * 4;
    const int te = (t & 15) * 4;
    float acc[4][4] = {};

    for (int chunk = 0; chunk < NCHUNK; chunk++) {
        __syncthreads();
#pragma unroll
        for (int r = 0; r < 4; r++) {
            int i4 = r * 256 + t;
            ((float4*)Bs)[i4] = ((const float4*)(W + chunk * 4096))[i4];
        }
        __syncthreads();

        // kron = l_i * r_j -> inner GEMM over r; linear-l chunk uses LsT, linear-r uses RsT
        const float* A = (chunk == 64) ? LsT : RsT;
        float P[4][4] = {};
#pragma unroll 8
        for (int j = 0; j < 64; j++) {
            float4 a = *(const float4*)(A + j * LPITCH + tm);
            float4 b = *(const float4*)(Bs + j * 64 + te);
            P[0][0] += a.x * b.x; P[0][1] += a.x * b.y; P[0][2] += a.x * b.z; P[0][3] += a.x * b.w;
            P[1][0] += a.y * b.x; P[1][1] += a.y * b.y; P[1][2] += a.y * b.z; P[1][3] += a.y * b.w;
            P[2][0] += a.z * b.x; P[2][1] += a.z * b.y; P[2][2] += a.z * b.z; P[2][3] += a.z * b.w;
            P[3][0] += a.w * b.x; P[3][1] += a.w * b.y; P[3][2] += a.w * b.z; P[3][3] += a.w * b.w;
        }
        if (chunk < 64) {
            float4 ai = *(const float4*)(LsT + chunk * LPITCH + tm);
            float am[4] = {ai.x, ai.y, ai.z, ai.w};
#pragma unroll
            for (int mm = 0; mm < 4; mm++)
#pragma unroll
                for (int nn = 0; nn < 4; nn++) acc[mm][nn] += am[mm] * P[mm][nn];
        } else {
#pragma unroll
            for (int mm = 0; mm < 4; mm++)
#pragma unroll
                for (int nn = 0; nn < 4; nn++) acc[mm][nn] += P[mm][nn];
        }
    }

    // leaky_relu, stage act transposed [e][m] into Bs (conflict-free column reads later)
    __syncthreads();
    {
        float4 bv = *(const float4*)(bias + te);
        float bb[4] = {bv.x, bv.y, bv.z, bv.w};
#pragma unroll
        for (int mm = 0; mm < 4; mm++)
#pragma unroll
            for (int nn = 0; nn < 4; nn++) {
                float v = acc[mm][nn] + bb[nn];
                v = (v > 0.f) ? v : 0.01f * v;
                Bs[(te + nn) * 64 + (tm + mm)] = v;
            }
    }
    __syncthreads();

    if (t < 64) {
        int m = t;
        float lg[NREL];
#pragma unroll
        for (int c = 0; c < NREL; c++) {
            float s = sm_b[c];
#pragma unroll 8
            for (int e = 0; e < 64; e++) s += Bs[e * 64 + m] * sm_w[c * 64 + e];
            lg[c] = s;
        }
        float mx = lg[0];
#pragma unroll
        for (int c = 1; c < NREL; c++) mx = fmaxf(mx, lg[c]);
        float sum = 0.f;
#pragma unroll
        for (int c = 0; c < NREL; c++) { lg[c] = expf(lg[c] - mx); sum += lg[c]; }
        float inv = 1.f / sum;
#pragma unroll
        for (int c = 0; c < NREL; c++) out[(g0 + m) * NREL + c] = lg[c] * inv;
    }
}

// -------- launcher --------
extern "C" void kernel_launch(void* const* d_in, const int* in_sizes, int n_in,
                              void* d_out, int out_size) {
    (void)in_sizes; (void)n_in; (void)out_size;
    const int*   left   = (const int*)d_in[0];
    const int*   right  = (const int*)d_in[1];
    const float* voc_w  = (const float*)d_in[2];
    const float* voc_b  = (const float*)d_in[3];
    const float* cps_w  = (const float*)d_in[4];
    const float* cps_b  = (const float*)d_in[5];
    const float* cpst_w = (const float*)d_in[6];
    const float* cpst_b = (const float*)d_in[7];
    const float* cpr_w  = (const float*)d_in[8];
    const float* cpr_b  = (const float*)d_in[9];
    const float* cprt_w = (const float*)d_in[10];
    const float* cprt_b = (const float*)d_in[11];
    const float* sm_w   = (const float*)d_in[12];
    const float* sm_b   = (const float*)d_in[13];
    float* out = (float*)d_out;

    float *XA, *XB, *Wc, *Wf, *bc, *bf;
    cudaGetSymbolAddress((void**)&XA, g_XA);
    cudaGetSymbolAddress((void**)&XB, g_XB);
    cudaGetSymbolAddress((void**)&Wc, g_Wc);
    cudaGetSymbolAddress((void**)&Wf, g_Wf);
    cudaGetSymbolAddress((void**)&bc, g_bc);
    cudaGetSymbolAddress((void**)&bf, g_bf);

    const int SMEM = (2 * 64 * LPITCH + 4096) * (int)sizeof(float);  // 51200 B
    cudaFuncSetAttribute(k_compose, cudaFuncAttributeMaxDynamicSharedMemorySize, SMEM);
    cudaFuncSetAttribute(k_final,   cudaFuncAttributeMaxDynamicSharedMemorySize, SMEM);

    k_transpose_voc<<<(VOC + 63) / 64, 256>>>(voc_w);
    k_prep<<<(KTOT * D + 255) / 256, 256>>>(cps_w, cps_b, cpst_w, cpst_b,
                                            cpr_w, cpr_b, cprt_w, cprt_b);
    k_embed<<<(2 * BATCH * NLEAVES * 16) / 256, 256>>>(left, right, voc_b);

    k_compose<<<1024, 256, SMEM>>>(XA, XB, Wc, bc, 32);
    k_compose<<< 512, 256, SMEM>>>(XB, XA, Wc, bc, 16);
    k_compose<<< 256, 256, SMEM>>>(XA, XB, Wc, bc, 8);
    k_compose<<< 128, 256, SMEM>>>(XB, XA, Wc, bc, 4);
    k_compose<<<  64, 256, SMEM>>>(XA, XB, Wc, bc, 2);
    k_compose<<<  32, 256, SMEM>>>(XB, XA, Wc, bc, 1);

    k_final<<<BATCH / 64, 256, SMEM>>>(XA, out, Wf, bf, sm_w, sm_b);
}

// round 2
// speedup vs baseline: 1.7443x; 1.7443x over previous
#include <cuda_runtime.h>
#include <math.h>

#define BATCH   1024
#define D       64
#define NLEAVES 64
#define VOC     50000
#define NREL    7
#define KTOT    4224     // full (final): 4096 kron + 64 L-linear + 64 R-linear
#define SYMROWS 2304     // folded (compose): 2176 padded-triangular + 128 linear
#define LIN0    2176
#define LPITCH  68       // padded row pitch (floats) for transposed L/R tiles

// -------- device scratch (no runtime allocation allowed) --------
__device__ float g_vocT[VOC * D];                     // transposed vocab
__device__ float g_XA[2 * BATCH * NLEAVES * D];       // ping
__device__ float g_XB[2 * BATCH * (NLEAVES / 2) * D]; // pong
__device__ float g_Wc[SYMROWS * D];                   // folded compose weights [k][e]
__device__ float g_Wf[KTOT * D];                      // final weights [k][e]
__device__ float g_bc[D];
__device__ float g_bf[D];
__device__ float g_part[8 * 64 * 4096];               // K-split partials (2 MB)

// triangular base row of chunk i (rows padded to multiple of 4)
__device__ __host__ __forceinline__ int tri_base(int i) {
    int a = i >> 2, b = i & 3;
    return 4 * (a + 1) * (2 * a + b);
}

// -------- vocab transpose: (64, 50000) -> (50000, 64) --------
__global__ void k_transpose_voc(const float* __restrict__ voc_w) {
    __shared__ float tile[64][65];
    int v0 = blockIdx.x * 64;
    for (int idx = threadIdx.x; idx < 64 * 64; idx += 256) {
        int d = idx >> 6, vv = idx & 63;
        int v = v0 + vv;
        tile[vv][d] = (v < VOC) ? voc_w[d * VOC + v] : 0.f;
    }
    __syncthreads();
    for (int idx = threadIdx.x; idx < 64 * 64; idx += 256) {
        int vv = idx >> 6, d = idx & 63;
        int v = v0 + vv;
        if (v < VOC) g_vocT[v * D + d] = tile[vv][d];
    }
}

// -------- weight prep --------
// blocks 0..63 : folded symmetric compose chunks
// block  64    : compose linear rows + biases
// blocks 65+   : full final weights (transpose)
__global__ void k_prep(const float* __restrict__ cps_w,  const float* __restrict__ cps_b,
                       const float* __restrict__ cpst_w, const float* __restrict__ cpst_b,
                       const float* __restrict__ cpr_w,  const float* __restrict__ cpr_b,
                       const float* __restrict__ cprt_w, const float* __restrict__ cprt_b) {
    int blk = blockIdx.x;
    if (blk < 64) {
        int i = blk;
        int pad = (i + 4) & ~3;
        int base = tri_base(i);
        for (int idx = threadIdx.x; idx < pad * 64; idx += 256) {
            int j = idx >> 6, e = idx & 63;
            float v = 0.f;
            if (j < i)       v = cpst_w[e * 4096 + i * 64 + j] + cpst_w[e * 4096 + j * 64 + i];
            else if (j == i) v = cpst_w[e * 4096 + i * 65];
            g_Wc[(base + j) * 64 + e] = v;
        }
    } else if (blk == 64) {
        for (int idx = threadIdx.x; idx < 128 * 64; idx += 256) {
            int f = idx >> 6, e = idx & 63;
            g_Wc[(LIN0 + f) * 64 + e] = cps_w[e * 128 + f];
        }
        if (threadIdx.x < 64) {
            g_bc[threadIdx.x] = cps_b[threadIdx.x] + cpst_b[threadIdx.x];
            g_bf[threadIdx.x] = cpr_b[threadIdx.x] + cprt_b[threadIdx.x];
        }
    } else {
        int t = (blk - 65) * 256 + threadIdx.x;
        if (t < KTOT * D) {
            int e = t / KTOT, k = t % KTOT;
            float vf;
            if (k < 4096) vf = cprt_w[e * 4096 + k];
            else          vf = cpr_w[e * 128 + (k - 4096)];
            g_Wf[k * D + e] = vf;
        }
    }
}

// -------- embedding gather --------
__global__ void k_embed(const int* __restrict__ left, const int* __restrict__ right,
                        const float* __restrict__ voc_b) {
    int t = blockIdx.x * 256 + threadIdx.x;
    int node = t >> 4;
    int c = (t & 15) * 4;
    int tree = node >> 16;
    int bl = node & 0xFFFF;
    int idx = tree ? right[bl] : left[bl];
    float4 v  = *(const float4*)(g_vocT + idx * D + c);
    float4 bb = *(const float4*)(voc_b + c);
    v.x += bb.x; v.y += bb.y; v.z += bb.z; v.w += bb.w;
    *(float4*)(g_XA + node * D + c) = v;
}

#define GEMM_STEP(jj)                                                             \
    {                                                                             \
        float4 a = *(const float4*)(A + (j + jj) * LPITCH + tm);                  \
        float4 b = *(const float4*)(Bs + (j + jj) * 64 + te);                     \
        P[0][0] += a.x*b.x; P[0][1] += a.x*b.y; P[0][2] += a.x*b.z; P[0][3] += a.x*b.w; \
        P[1][0] += a.y*b.x; P[1][1] += a.y*b.y; P[1][2] += a.y*b.z; P[1][3] += a.y*b.w; \
        P[2][0] += a.z*b.x; P[2][1] += a.z*b.y; P[2][2] += a.z*b.z; P[2][3] += a.z*b.w; \
        P[3][0] += a.w*b.x; P[3][1] += a.w*b.y; P[3][2] += a.w*b.z; P[3][3] += a.w*b.w; \
    }

// -------- one tree-compose level (symmetric-folded), optional K-split --------
__global__ void __launch_bounds__(256) k_compose(const float* __restrict__ Xin,
                                                 float* __restrict__ Xout,
                                                 float* __restrict__ part,
                                                 const float* __restrict__ W,
                                                 const float* __restrict__ bias,
                                                 int n_out, int split, int ntiles) {
    extern __shared__ float smem[];
    float* LsT = smem;
    float* RsT = smem + 64 * LPITCH;
    float* Bs  = smem + 2 * 64 * LPITCH;
    const int t    = threadIdx.x;
    const int s    = blockIdx.x % split;
    const int tile = blockIdx.x / split;
    const int g0   = tile * 64;

    {   // load 64 pair-nodes, transpose into SMEM
        int m  = t >> 2;
        int fb = (t & 3) * 32;
        int g  = g0 + m;
        int p  = g % n_out;
        int bp = g / n_out;
        const float* src = Xin + (bp * 2 * n_out + 2 * p) * D;
#pragma unroll
        for (int it = 0; it < 8; it++) {
            int f = fb + it * 4;
            float4 v = *(const float4*)(src + f);
            float* dst = (f < 64) ? (LsT + f * LPITCH + m) : (RsT + (f - 64) * LPITCH + m);
            dst[0] = v.x; dst[LPITCH] = v.y; dst[2 * LPITCH] = v.z; dst[3 * LPITCH] = v.w;
        }
    }

    const int tm = (t >> 4) * 4;
    const int te = (t & 15) * 4;
    float acc[4][4] = {};

    for (int c = s; c < 66; c += split) {
        int rows, base;
        const float* A;
        if (c < 64) { rows = (c + 4) & ~3; base = tri_base(c); A = LsT; }
        else        { rows = 64; base = LIN0 + (c - 64) * 64; A = (c == 64) ? LsT : RsT; }

        __syncthreads();
        {
            int n4 = rows * 16;
            const float4* srcw = (const float4*)(W + base * 64);
            for (int u = t; u < n4; u += 256) ((float4*)Bs)[u] = srcw[u];
        }
        __syncthreads();

        float P[4][4] = {};
        for (int j = 0; j < rows; j += 4) {
            GEMM_STEP(0) GEMM_STEP(1) GEMM_STEP(2) GEMM_STEP(3)
        }
        if (c < 64) {
            float4 ai = *(const float4*)(LsT + c * LPITCH + tm);
            float am[4] = {ai.x, ai.y, ai.z, ai.w};
#pragma unroll
            for (int mm = 0; mm < 4; mm++)
#pragma unroll
                for (int nn = 0; nn < 4; nn++) acc[mm][nn] += am[mm] * P[mm][nn];
        } else {
#pragma unroll
            for (int mm = 0; mm < 4; mm++)
#pragma unroll
                for (int nn = 0; nn < 4; nn++) acc[mm][nn] += P[mm][nn];
        }
    }

    if (split == 1) {
        float4 bv = *(const float4*)(bias + te);
        float bb[4] = {bv.x, bv.y, bv.z, bv.w};
#pragma unroll
        for (int mm = 0; mm < 4; mm++) {
            float4 o;
            o.x = tanhf(acc[mm][0] + bb[0]);
            o.y = tanhf(acc[mm][1] + bb[1]);
            o.z = tanhf(acc[mm][2] + bb[2]);
            o.w = tanhf(acc[mm][3] + bb[3]);
            *(float4*)(Xout + (g0 + tm + mm) * D + te) = o;
        }
    } else {
        float* dst = part + (size_t)(s * ntiles + tile) * 4096;
#pragma unroll
        for (int mm = 0; mm < 4; mm++)
#pragma unroll
            for (int nn = 0; nn < 4; nn++) dst[(tm + mm) * 64 + (te + nn)] = acc[mm][nn];
    }
}

// -------- sum K-split partials + bias + tanh --------
__global__ void __launch_bounds__(256) k_reduce(const float* __restrict__ part,
                                                float* __restrict__ Xout,
                                                const float* __restrict__ bias,
                                                int ntiles, int split) {
    int tile = blockIdx.x;
    for (int idx = threadIdx.x; idx < 4096; idx += 256) {
        float sum = 0.f;
        for (int s = 0; s < split; s++) sum += part[(size_t)(s * ntiles + tile) * 4096 + idx];
        Xout[(size_t)tile * 4096 + idx] = tanhf(sum + bias[idx & 63]);
    }
}

// -------- final matmuls (asymmetric kron = l (x) r), K-split partials --------
__global__ void __launch_bounds__(256) k_final_part(const float* __restrict__ X,
                                                    float* __restrict__ part,
                                                    const float* __restrict__ W,
                                                    int split) {
    extern __shared__ float smem[];
    float* LsT = smem;
    float* RsT = smem + 64 * LPITCH;
    float* Bs  = smem + 2 * 64 * LPITCH;
    const int t    = threadIdx.x;
    const int s    = blockIdx.x % split;
    const int tile = blockIdx.x / split;
    const int g0   = tile * 64;

    {
        int m  = t >> 2;
        int fb = (t & 3) * 32;
        int b  = g0 + m;
#pragma unroll
        for (int it = 0; it < 8; it++) {
            int f = fb + it * 4;
            const float* src = (f < 64) ? (X + b * D + f) : (X + (BATCH + b) * D + (f - 64));
            float4 v = *(const float4*)src;
            float* dst = (f < 64) ? (LsT + f * LPITCH + m) : (RsT + (f - 64) * LPITCH + m);
            dst[0] = v.x; dst[LPITCH] = v.y; dst[2 * LPITCH] = v.z; dst[3 * LPITCH] = v.w;
        }
    }

    const int tm = (t >> 4) * 4;
    const int te = (t & 15) * 4;
    float acc[4][4] = {};

    for (int c = s; c < 66; c += split) {
        __syncthreads();
#pragma unroll
        for (int r = 0; r < 4; r++) {
            int i4 = r * 256 + t;
            ((float4*)Bs)[i4] = ((const float4*)(W + c * 4096))[i4];
        }
        __syncthreads();

        const float* A = (c == 64) ? LsT : RsT;
        float P[4][4] = {};
        for (int j = 0; j < 64; j += 4) {
            GEMM_STEP(0) GEMM_STEP(1) GEMM_STEP(2) GEMM_STEP(3)
        }
        if (c < 64) {
            float4 ai = *(const float4*)(LsT + c * LPITCH + tm);
            float am[4] = {ai.x, ai.y, ai.z, ai.w};
#pragma unroll
            for (int mm = 0; mm < 4; mm++)
#pragma unroll
                for (int nn = 0; nn < 4; nn++) acc[mm][nn] += am[mm] * P[mm][nn];
        } else {
#pragma unroll
            for (int mm = 0; mm < 4; mm++)
#pragma unroll
                for (int nn = 0; nn < 4; nn++) acc[mm][nn] += P[mm][nn];
        }
    }

    float* dst = part + (size_t)(s * (BATCH / 64) + tile) * 4096;
#pragma unroll
    for (int mm = 0; mm < 4; mm++)
#pragma unroll
        for (int nn = 0; nn < 4; nn++) dst[(tm + mm) * 64 + (te + nn)] = acc[mm][nn];
}

// -------- final epilogue: reduce + bias + leaky + logits + softmax --------
__global__ void __launch_bounds__(256) k_final_reduce(const float* __restrict__ part,
                                                      float* __restrict__ out,
                                                      const float* __restrict__ bias,
                                                      const float* __restrict__ sm_w,
                                                      const float* __restrict__ sm_b,
                                                      int split) {
    __shared__ float actT[64 * 65];   // [e][m], pitch 65
    const int tile = blockIdx.x;      // BATCH/64 tiles
    const int t = threadIdx.x;
    const int ntiles = BATCH / 64;

    for (int idx = t; idx < 4096; idx += 256) {
        float sum = 0.f;
        for (int s = 0; s < split; s++) sum += part[(size_t)(s * ntiles + tile) * 4096 + idx];
        sum += bias[idx & 63];
        sum = (sum > 0.f) ? sum : 0.01f * sum;
        actT[(idx & 63) * 65 + (idx >> 6)] = sum;
    }
    __syncthreads();

    if (t < 64) {
        int m = t;
        float lg[NREL];
#pragma unroll
        for (int c = 0; c < NREL; c++) {
            float ssum = sm_b[c];
#pragma unroll 8
            for (int e = 0; e < 64; e++) ssum += actT[e * 65 + m] * sm_w[c * 64 + e];
            lg[c] = ssum;
        }
        float mx = lg[0];
#pragma unroll
        for (int c = 1; c < NREL; c++) mx = fmaxf(mx, lg[c]);
        float sum = 0.f;
#pragma unroll
        for (int c = 0; c < NREL; c++) { lg[c] = expf(lg[c] - mx); sum += lg[c]; }
        float inv = 1.f / sum;
#pragma unroll
        for (int c = 0; c < NREL; c++) out[(tile * 64 + m) * NREL + c] = lg[c] * inv;
    }
}

// -------- launcher --------
extern "C" void kernel_launch(void* const* d_in, const int* in_sizes, int n_in,
                              void* d_out, int out_size) {
    (void)in_sizes; (void)n_in; (void)out_size;
    const int*   left   = (const int*)d_in[0];
    const int*   right  = (const int*)d_in[1];
    const float* voc_w  = (const float*)d_in[2];
    const float* voc_b  = (const float*)d_in[3];
    const float* cps_w  = (const float*)d_in[4];
    const float* cps_b  = (const float*)d_in[5];
    const float* cpst_w = (const float*)d_in[6];
    const float* cpst_b = (const float*)d_in[7];
    const float* cpr_w  = (const float*)d_in[8];
    const float* cpr_b  = (const float*)d_in[9];
    const float* cprt_w = (const float*)d_in[10];
    const float* cprt_b = (const float*)d_in[11];
    const float* sm_w   = (const float*)d_in[12];
    const float* sm_b   = (const float*)d_in[13];
    float* out = (float*)d_out;

    float *XA, *XB, *Wc, *Wf, *bc, *bf, *part;
    cudaGetSymbolAddress((void**)&XA, g_XA);
    cudaGetSymbolAddress((void**)&XB, g_XB);
    cudaGetSymbolAddress((void**)&Wc, g_Wc);
    cudaGetSymbolAddress((void**)&Wf, g_Wf);
    cudaGetSymbolAddress((void**)&bc, g_bc);
    cudaGetSymbolAddress((void**)&bf, g_bf);
    cudaGetSymbolAddress((void**)&part, g_part);

    const int SMEM = (2 * 64 * LPITCH + 4096) * (int)sizeof(float);  // 51200 B
    cudaFuncSetAttribute(k_compose,    cudaFuncAttributeMaxDynamicSharedMemorySize, SMEM);
    cudaFuncSetAttribute(k_final_part, cudaFuncAttributeMaxDynamicSharedMemorySize, SMEM);

    k_transpose_voc<<<(VOC + 63) / 64, 256>>>(voc_w);
    k_prep<<<65 + (KTOT * D + 255) / 256, 256>>>(cps_w, cps_b, cpst_w, cpst_b,
                                                 cpr_w, cpr_b, cprt_w, cprt_b);
    k_embed<<<(2 * BATCH * NLEAVES * 16) / 256, 256>>>(left, right, voc_b);

    // levels 1..4: plenty of blocks, no split
    k_compose<<<1024, 256, SMEM>>>(XA, XB, part, Wc, bc, 32, 1, 1024);
    k_compose<<< 512, 256, SMEM>>>(XB, XA, part, Wc, bc, 16, 1, 512);
    k_compose<<< 256, 256, SMEM>>>(XA, XB, part, Wc, bc, 8, 1, 256);
    k_compose<<< 128, 256, SMEM>>>(XB, XA, part, Wc, bc, 4, 1, 128);
    // level 5: 64 tiles, K-split 2
    k_compose<<< 128, 256, SMEM>>>(XA, XB, part, Wc, bc, 2, 2, 64);
    k_reduce<<<64, 256>>>(part, XB, bc, 64, 2);
    // level 6: 32 tiles, K-split 4
    k_compose<<< 128, 256, SMEM>>>(XB, XA, part, Wc, bc, 1, 4, 32);
    k_reduce<<<32, 256>>>(part, XA, bc, 32, 4);
    // final: 16 tiles, K-split 8
    k_final_part<<<128, 256, SMEM>>>(XA, part, Wf, 8);
    k_final_reduce<<<BATCH / 64, 256>>>(part, out, bf, sm_w, sm_b, 8);
}